// round 15
// baseline (speedup 1.0000x reference)
#include <cuda_runtime.h>
#include <math.h>

#define BB 32
#define TT 1024
#define VV 5000
#define STEPS 64
#define JPAD 5008
#define NP 64            // attention T-parts
#define TCH 16           // t-chunk per part
#define GKS 8            // gates K-split
#define LKS 4            // logits K-split
#define HKS 8            // hid K-split (chunk 128)

// ---------------- persistent device state ----------------
__device__ float g_actT[1536 * BB];          // [emb|ctx|h] transposed [k][b]
__device__ float g_hcT[1024 * BB];           // [h|ctx] transposed
__device__ float g_hRow[BB * 512];           // h row-major [b][i]
__device__ float g_cT[512 * BB];
__device__ float g_gatesP[GKS][2048 * BB];
__device__ float g_hidP[HKS][512 * BB];      // hid partials [j][b]
__device__ float g_hidT[512 * BB];
__device__ float g_logitsP[LKS][BB * JPAD];
__device__ float g_eBuf[BB * TT];
__device__ float g_mP[NP * 128];
__device__ float g_sP[NP * 128];
__device__ float g_ctxP[NP][128 * 128];

// ---------------- init ----------------
__global__ void init_kernel(const float* __restrict__ emb, const float* __restrict__ lf)
{
    int idx = blockIdx.x * blockDim.x + threadIdx.x;
    if (idx >= 1536 * BB) return;
    int b = idx & 31, k = idx >> 5;
    float v;
    if (k < 512)       v = emb[k];
    else if (k < 1024) v = lf[(size_t)b * TT * 512 + (k - 512)];
    else             { v = 0.f; g_cT[(k - 1024) * BB + b] = 0.f; }
    g_actT[idx] = v;
}

// ---------------- gates GEMM, K-split x8, padded smem ----------------
__global__ void gates_gemm_kernel(const float* __restrict__ W_ih,
                                  const float* __restrict__ W_hh)
{
    __shared__ float ws[16 * 193];
    const int j0 = blockIdx.x * 16;
    const int base = blockIdx.y * 192;
    for (int idx = threadIdx.x; idx < 16 * 192; idx += 128) {
        int r = idx / 192, kk = idx - r * 192;
        int k = base + kk, j = j0 + r;
        ws[r * 193 + kk] = (k < 1024) ? W_ih[(size_t)j * 1024 + k]
                                      : W_hh[(size_t)j * 512 + (k - 1024)];
    }
    __syncthreads();

    int bg = threadIdx.x & 7, jj = threadIdx.x >> 3;
    const float* wr = ws + jj * 193;
    const float4* xv = (const float4*)g_actT;
    float ax = 0.f, ay = 0.f, az = 0.f, aw = 0.f;
    #pragma unroll 8
    for (int kk = 0; kk < 192; kk++) {
        float w = wr[kk];
        float4 x = xv[(base + kk) * 8 + bg];
        ax = fmaf(w, x.x, ax); ay = fmaf(w, x.y, ay);
        az = fmaf(w, x.z, az); aw = fmaf(w, x.w, aw);
    }
    ((float4*)g_gatesP[blockIdx.y])[(j0 + jj) * 8 + bg] = make_float4(ax, ay, az, aw);
}

// ---------------- LSTM pointwise (float4 over batch) ----------------
__global__ void lstm_pointwise_kernel(const float* __restrict__ b_ih,
                                      const float* __restrict__ b_hh)
{
    int idx = blockIdx.x * blockDim.x + threadIdx.x;   // 4096
    if (idx >= 512 * 8) return;
    int b4 = idx & 7, i = idx >> 3;

    float4 g4[4];
    #pragma unroll
    for (int g = 0; g < 4; g++) {
        int j = g * 512 + i;
        float bias = b_ih[j] + b_hh[j];
        float4 v = make_float4(bias, bias, bias, bias);
        #pragma unroll
        for (int p = 0; p < GKS; p++) {
            float4 x = ((const float4*)g_gatesP[p])[j * 8 + b4];
            v.x += x.x; v.y += x.y; v.z += x.z; v.w += x.w;
        }
        g4[g] = v;
    }
    float4 c = ((const float4*)g_cT)[i * 8 + b4];
    float4 hv;
    {
        float cc, h;
        #define DO_LANE(L) { \
            float si = 1.f / (1.f + __expf(-g4[0].L)); \
            float sf = 1.f / (1.f + __expf(-g4[1].L)); \
            float tg = tanhf(g4[2].L); \
            float so = 1.f / (1.f + __expf(-g4[3].L)); \
            cc = sf * c.L + si * tg; c.L = cc; \
            h = so * tanhf(cc); hv.L = h; }
        DO_LANE(x) DO_LANE(y) DO_LANE(z) DO_LANE(w)
        #undef DO_LANE
    }
    ((float4*)g_cT)[i * 8 + b4] = c;
    ((float4*)(g_actT + 1024 * BB))[i * 8 + b4] = hv;
    ((float4*)g_hcT)[i * 8 + b4] = hv;
    int b0 = b4 * 4;
    g_hRow[(b0 + 0) * 512 + i] = hv.x;
    g_hRow[(b0 + 1) * 512 + i] = hv.y;
    g_hRow[(b0 + 2) * 512 + i] = hv.z;
    g_hRow[(b0 + 3) * 512 + i] = hv.w;
}

// ------ attention partials: register-direct, warp = 2 timesteps ------
// block = (b, head) x part(64); warp w owns t = part*16 + w*2 .. +2
__global__ void __launch_bounds__(256, 8)
attn_part_kernel(const float* __restrict__ lf)
{
    __shared__ float e_s[TCH];
    __shared__ __align__(16) float csh[8 * 132];
    int b = blockIdx.x & 31, hh = blockIdx.x >> 5;
    int part = blockIdx.y;
    int t0 = part * TCH;
    int tid = threadIdx.x, lane = tid & 31, w = tid >> 5;

    float4 ds4 = ((const float4*)(g_hRow + b * 512 + hh * 128))[lane];

    const float4* src = (const float4*)(lf + ((size_t)b * TT + t0) * 512 + hh * 128);
    float4 v0 = src[(size_t)(w * 2 + 0) * 128 + lane];
    float4 v1 = src[(size_t)(w * 2 + 1) * 128 + lane];

    float a0 = ds4.x * v0.x + ds4.y * v0.y + ds4.z * v0.z + ds4.w * v0.w;
    float a1 = ds4.x * v1.x + ds4.y * v1.y + ds4.z * v1.z + ds4.w * v1.w;
    #pragma unroll
    for (int off = 16; off; off >>= 1) {
        a0 += __shfl_xor_sync(~0u, a0, off);
        a1 += __shfl_xor_sync(~0u, a1, off);
    }
    if (lane == 0) { e_s[w * 2 + 0] = a0; e_s[w * 2 + 1] = a1; }
    __syncthreads();

    int bh = b * 4 + hh;
    if (tid < 32) {
        float e = (tid < TCH) ? e_s[tid] : -1e30f;
        if (hh == 3 && tid < TCH) g_eBuf[b * TT + t0 + tid] = e;
        float m = e;
        #pragma unroll
        for (int off = 16; off; off >>= 1) m = fmaxf(m, __shfl_xor_sync(~0u, m, off));
        float p = (tid < TCH) ? __expf(e - m) : 0.f;
        if (tid < TCH) e_s[tid] = p;
        float s = p;
        #pragma unroll
        for (int off = 16; off; off >>= 1) s += __shfl_xor_sync(~0u, s, off);
        if (tid == 0) { g_mP[part * 128 + bh] = m; g_sP[part * 128 + bh] = s; }
    }
    __syncthreads();

    float p0 = e_s[w * 2 + 0], p1 = e_s[w * 2 + 1];
    float4 acc;
    acc.x = p0 * v0.x + p1 * v1.x;
    acc.y = p0 * v0.y + p1 * v1.y;
    acc.z = p0 * v0.z + p1 * v1.z;
    acc.w = p0 * v0.w + p1 * v1.w;
    ((float4*)&csh[w * 132])[lane] = acc;
    __syncthreads();

    if (tid < 128) {
        float ss = 0.f;
        #pragma unroll
        for (int q = 0; q < 8; q++) ss += csh[q * 132 + tid];
        g_ctxP[part][bh * 128 + tid] = ss;
    }
}

// ---------------- attention combine (NP=64) ----------------
__global__ void attn_combine_kernel(float* __restrict__ attn_out)
{
    int b = blockIdx.x & 31, hh = blockIdx.x >> 5;
    int bh = b * 4 + hh;
    int tid = threadIdx.x;   // 128
    __shared__ float m_s[NP];
    __shared__ float w_s[NP];
    __shared__ float Ms, Ss;

    if (tid < NP) m_s[tid] = g_mP[tid * 128 + bh];
    __syncthreads();
    if (tid < 32) {
        float m = fmaxf(m_s[tid], m_s[tid + 32]);
        float M = m;
        #pragma unroll
        for (int off = 16; off; off >>= 1) M = fmaxf(M, __shfl_xor_sync(~0u, M, off));
        float w0 = __expf(m_s[tid] - M);
        float w1 = __expf(m_s[tid + 32] - M);
        w_s[tid] = w0;
        w_s[tid + 32] = w1;
        float s = g_sP[tid * 128 + bh] * w0 + g_sP[(tid + 32) * 128 + bh] * w1;
        #pragma unroll
        for (int off = 16; off; off >>= 1) s += __shfl_xor_sync(~0u, s, off);
        if (tid == 0) { Ms = M; Ss = s; }
    }
    __syncthreads();
    float inv = 1.f / Ss;
    float M = Ms;

    float ctx = 0.f;
    #pragma unroll
    for (int p = 0; p < NP; p++) ctx = fmaf(g_ctxP[p][bh * 128 + tid], w_s[p], ctx);
    ctx *= inv;
    int d = hh * 128 + tid;
    g_actT[(512 + d) * BB + b] = ctx;
    g_hcT[(512 + d) * BB + b] = ctx;

    if (hh == 3) {
        #pragma unroll
        for (int i = 0; i < 8; i++) {
            int t = tid + i * 128;
            __stcs(&attn_out[(size_t)b * TT + t], __expf(g_eBuf[b * TT + t] - M) * inv);
        }
    }
}

// ------- predict_hid split GEMM: K-split x8, smem-staged weights -------
__global__ void hid_split_kernel(const float* __restrict__ Wp)
{
    __shared__ float ws[16 * 129];
    const int j0 = blockIdx.x * 16;       // 32 j-tiles
    const int base = blockIdx.y * 128;    // 8 K-parts
    for (int idx = threadIdx.x; idx < 16 * 128; idx += 128) {
        int r = idx >> 7, kk = idx & 127;
        ws[r * 129 + kk] = Wp[(size_t)(j0 + r) * 1024 + base + kk];
    }
    __syncthreads();

    int bg = threadIdx.x & 7, jj = threadIdx.x >> 3;
    const float* wr = ws + jj * 129;
    const float4* xv = (const float4*)g_hcT;
    float ax = 0.f, ay = 0.f, az = 0.f, aw = 0.f;
    #pragma unroll 8
    for (int kk = 0; kk < 128; kk++) {
        float w = wr[kk];
        float4 x = xv[(base + kk) * 8 + bg];
        ax = fmaf(w, x.x, ax); ay = fmaf(w, x.y, ay);
        az = fmaf(w, x.z, az); aw = fmaf(w, x.w, aw);
    }
    ((float4*)g_hidP[blockIdx.y])[(j0 + jj) * 8 + bg] = make_float4(ax, ay, az, aw);
}

// ------- hid reduce: sum 8 partials + bias + relu -------
__global__ void hid_reduce_kernel(const float* __restrict__ bp)
{
    int idx = blockIdx.x * blockDim.x + threadIdx.x;   // 4096 float4 items
    if (idx >= 512 * 8) return;
    int j = idx >> 3;
    float4 v = make_float4(0.f, 0.f, 0.f, 0.f);
    #pragma unroll
    for (int p = 0; p < HKS; p++) {
        float4 x = ((const float4*)g_hidP[p])[idx];
        v.x += x.x; v.y += x.y; v.z += x.z; v.w += x.w;
    }
    float bias = bp[j];
    v.x = fmaxf(v.x + bias, 0.f); v.y = fmaxf(v.y + bias, 0.f);
    v.z = fmaxf(v.z + bias, 0.f); v.w = fmaxf(v.w + bias, 0.f);
    ((float4*)g_hidT)[idx] = v;
}

// ---------------- logits GEMM, K-split x4, padded smem ----------------
__global__ void logits_gemm_kernel(const float* __restrict__ Wc)
{
    __shared__ float ws[16 * 129];
    const int j0 = blockIdx.x * 16;
    const int base = blockIdx.y * 128;
    for (int idx = threadIdx.x; idx < 16 * 128; idx += 128) {
        int r = idx >> 7, kk = idx & 127;
        int j = j0 + r;
        ws[r * 129 + kk] = (j < VV) ? Wc[(size_t)j * 512 + base + kk] : 0.f;
    }
    __syncthreads();

    int bg = threadIdx.x & 7, jj = threadIdx.x >> 3;
    int j = j0 + jj;
    const float* wr = ws + jj * 129;
    const float4* xv = (const float4*)g_hidT;
    float ax = 0.f, ay = 0.f, az = 0.f, aw = 0.f;
    #pragma unroll 8
    for (int kk = 0; kk < 128; kk++) {
        float w = wr[kk];
        float4 x = xv[(base + kk) * 8 + bg];
        ax = fmaf(w, x.x, ax); ay = fmaf(w, x.y, ay);
        az = fmaf(w, x.z, az); aw = fmaf(w, x.w, aw);
    }
    if (j < VV) {
        float* dst = g_logitsP[blockIdx.y];
        int b0 = bg * 4;
        dst[(size_t)(b0 + 0) * JPAD + j] = ax;
        dst[(size_t)(b0 + 1) * JPAD + j] = ay;
        dst[(size_t)(b0 + 2) * JPAD + j] = az;
        dst[(size_t)(b0 + 3) * JPAD + j] = aw;
    }
}

// ------- log_softmax + argmax + pred row + next embedding -----
__global__ void lsm_kernel(const float* __restrict__ bc, const float* __restrict__ emb,
                           float* __restrict__ out_pred)
{
    int b = blockIdx.x;
    int tid = threadIdx.x;   // 1024
    __shared__ float v_s[VV];
    __shared__ float sv[1024];
    __shared__ int   si[1024];
    __shared__ int   tok_s;

    const float4* p0 = (const float4*)(g_logitsP[0] + (size_t)b * JPAD);
    const float4* p1 = (const float4*)(g_logitsP[1] + (size_t)b * JPAD);
    const float4* p2 = (const float4*)(g_logitsP[2] + (size_t)b * JPAD);
    const float4* p3 = (const float4*)(g_logitsP[3] + (size_t)b * JPAD);
    const float4* bcv = (const float4*)bc;
    for (int j4 = tid; j4 < VV / 4; j4 += 1024) {
        float4 a = p0[j4], c = p1[j4], d = p2[j4], e = p3[j4], f = bcv[j4];
        float4 r;
        r.x = a.x + c.x + d.x + e.x + f.x;
        r.y = a.y + c.y + d.y + e.y + f.y;
        r.z = a.z + c.z + d.z + e.z + f.z;
        r.w = a.w + c.w + d.w + e.w + f.w;
        ((float4*)v_s)[j4] = r;
    }
    __syncthreads();

    float m = -1e30f; int mi = VV;
    for (int j = tid; j < VV; j += 1024) {
        float v = v_s[j];
        if (v > m) { m = v; mi = j; }
    }
    sv[tid] = m; si[tid] = mi; __syncthreads();
    for (int st = 512; st; st >>= 1) {
        if (tid < st) {
            float v2 = sv[tid + st]; int i2 = si[tid + st];
            if (v2 > sv[tid] || (v2 == sv[tid] && i2 < si[tid])) { sv[tid] = v2; si[tid] = i2; }
        }
        __syncthreads();
    }
    float mm = sv[0];
    if (tid == 0) tok_s = si[0];
    __syncthreads();

    float s = 0.f;
    for (int j = tid; j < VV; j += 1024) s += __expf(v_s[j] - mm);
    sv[tid] = s; __syncthreads();
    for (int st = 512; st; st >>= 1) { if (tid < st) sv[tid] += sv[tid + st]; __syncthreads(); }
    float lse = mm + logf(sv[0]);

    float4* row = (float4*)(out_pred + (size_t)b * VV);
    for (int j4 = tid; j4 < VV / 4; j4 += 1024) {
        float4 v = ((float4*)v_s)[j4];
        v.x -= lse; v.y -= lse; v.z -= lse; v.w -= lse;
        __stcs(&row[j4], v);
    }

    int tok = tok_s;
    if (tid < 512) g_actT[tid * BB + b] = emb[(size_t)tok * 512 + tid];
}

// ---------------- launcher ----------------
extern "C" void kernel_launch(void* const* d_in, const int* in_sizes, int n_in,
                              void* d_out, int out_size)
{
    const float* lf   = (const float*)d_in[0];
    const float* emb  = (const float*)d_in[1];
    const float* W_ih = (const float*)d_in[2];
    const float* W_hh = (const float*)d_in[3];
    const float* b_ih = (const float*)d_in[4];
    const float* b_hh = (const float*)d_in[5];
    const float* Wp   = (const float*)d_in[6];
    const float* bp   = (const float*)d_in[7];
    const float* Wc   = (const float*)d_in[8];
    const float* bc   = (const float*)d_in[9];

    float* out      = (float*)d_out;
    float* out_pred = out;
    float* out_attn = out + (size_t)STEPS * BB * VV;

    init_kernel<<<192, 256>>>(emb, lf);

    for (int s = 0; s < STEPS; s++) {
        gates_gemm_kernel<<<dim3(128, GKS), 128>>>(W_ih, W_hh);
        lstm_pointwise_kernel<<<32, 128>>>(b_ih, b_hh);
        attn_part_kernel<<<dim3(128, NP), 256>>>(lf);
        attn_combine_kernel<<<128, 128>>>(out_attn + (size_t)s * BB * TT);
        hid_split_kernel<<<dim3(32, HKS), 128>>>(Wp);
        hid_reduce_kernel<<<16, 256>>>(bp);
        logits_gemm_kernel<<<dim3(313, LKS), 128>>>(Wc);
        lsm_kernel<<<32, 1024>>>(bc, emb, out_pred + (size_t)s * BB * VV);
    }
}

// round 16
// speedup vs baseline: 1.0194x; 1.0194x over previous
#include <cuda_runtime.h>
#include <math.h>

#define BB 32
#define TT 1024
#define VV 5000
#define STEPS 64
#define JPAD 5008
#define NP 32            // attention T-parts
#define TCH 32           // t-chunk per part
#define GKS 8            // gates K-split (chunk 192)
#define LKS 4            // logits K-split (chunk 128)
#define HKS 8            // hid K-split (chunk 128)

// ---------------- persistent device state ----------------
__device__ float g_actT[1536 * BB];          // [emb|ctx|h] transposed [k][b]
__device__ float g_hcT[1024 * BB];           // [h|ctx] transposed
__device__ float g_hRow[BB * 512];           // h row-major [b][i]
__device__ float g_cT[512 * BB];
__device__ float g_gatesP[GKS][2048 * BB];
__device__ float g_hidP[HKS][512 * BB];      // hid partials [j][b]
__device__ float g_hidT[512 * BB];
__device__ float g_logitsP[LKS][BB * JPAD];
__device__ float g_eBuf[BB * TT];
__device__ float g_mP[NP * 128];
__device__ float g_sP[NP * 128];
__device__ float g_ctxP[NP][128 * 128];

// ---------------- init ----------------
__global__ void init_kernel(const float* __restrict__ emb, const float* __restrict__ lf)
{
    int idx = blockIdx.x * blockDim.x + threadIdx.x;
    if (idx >= 1536 * BB) return;
    int b = idx & 31, k = idx >> 5;
    float v;
    if (k < 512)       v = emb[k];
    else if (k < 1024) v = lf[(size_t)b * TT * 512 + (k - 512)];
    else             { v = 0.f; g_cT[(k - 1024) * BB + b] = 0.f; }
    g_actT[idx] = v;
}

// -------- gates GEMM, K-split x8, 32 j/block, 2-j register blocking --------
__global__ void gates_gemm_kernel(const float* __restrict__ W_ih,
                                  const float* __restrict__ W_hh)
{
    __shared__ float ws[32 * 193];
    const int j0 = blockIdx.x * 32;
    const int base = blockIdx.y * 192;
    for (int idx = threadIdx.x; idx < 32 * 192; idx += 128) {
        int r = idx / 192, kk = idx - r * 192;
        int k = base + kk, j = j0 + r;
        ws[r * 193 + kk] = (k < 1024) ? W_ih[(size_t)j * 1024 + k]
                                      : W_hh[(size_t)j * 512 + (k - 1024)];
    }
    __syncthreads();

    int bg = threadIdx.x & 7, jp = threadIdx.x >> 3;   // jp 0..15
    const float* wr0 = ws + (jp * 2) * 193;
    const float* wr1 = wr0 + 193;
    const float4* xv = (const float4*)g_actT;
    float a0x = 0.f, a0y = 0.f, a0z = 0.f, a0w = 0.f;
    float a1x = 0.f, a1y = 0.f, a1z = 0.f, a1w = 0.f;
    #pragma unroll 8
    for (int kk = 0; kk < 192; kk++) {
        float w0 = wr0[kk], w1 = wr1[kk];
        float4 x = xv[(base + kk) * 8 + bg];
        a0x = fmaf(w0, x.x, a0x); a0y = fmaf(w0, x.y, a0y);
        a0z = fmaf(w0, x.z, a0z); a0w = fmaf(w0, x.w, a0w);
        a1x = fmaf(w1, x.x, a1x); a1y = fmaf(w1, x.y, a1y);
        a1z = fmaf(w1, x.z, a1z); a1w = fmaf(w1, x.w, a1w);
    }
    int j = j0 + jp * 2;
    ((float4*)g_gatesP[blockIdx.y])[j * 8 + bg]       = make_float4(a0x, a0y, a0z, a0w);
    ((float4*)g_gatesP[blockIdx.y])[(j + 1) * 8 + bg] = make_float4(a1x, a1y, a1z, a1w);
}

// ---------------- LSTM pointwise (float4 over batch) ----------------
__global__ void lstm_pointwise_kernel(const float* __restrict__ b_ih,
                                      const float* __restrict__ b_hh)
{
    int idx = blockIdx.x * blockDim.x + threadIdx.x;   // 4096
    if (idx >= 512 * 8) return;
    int b4 = idx & 7, i = idx >> 3;

    float4 g4[4];
    #pragma unroll
    for (int g = 0; g < 4; g++) {
        int j = g * 512 + i;
        float bias = b_ih[j] + b_hh[j];
        float4 v = make_float4(bias, bias, bias, bias);
        #pragma unroll
        for (int p = 0; p < GKS; p++) {
            float4 x = ((const float4*)g_gatesP[p])[j * 8 + b4];
            v.x += x.x; v.y += x.y; v.z += x.z; v.w += x.w;
        }
        g4[g] = v;
    }
    float4 c = ((const float4*)g_cT)[i * 8 + b4];
    float4 hv;
    {
        float cc, h;
        #define DO_LANE(L) { \
            float si = 1.f / (1.f + __expf(-g4[0].L)); \
            float sf = 1.f / (1.f + __expf(-g4[1].L)); \
            float tg = tanhf(g4[2].L); \
            float so = 1.f / (1.f + __expf(-g4[3].L)); \
            cc = sf * c.L + si * tg; c.L = cc; \
            h = so * tanhf(cc); hv.L = h; }
        DO_LANE(x) DO_LANE(y) DO_LANE(z) DO_LANE(w)
        #undef DO_LANE
    }
    ((float4*)g_cT)[i * 8 + b4] = c;
    ((float4*)(g_actT + 1024 * BB))[i * 8 + b4] = hv;
    ((float4*)g_hcT)[i * 8 + b4] = hv;
    int b0 = b4 * 4;
    g_hRow[(b0 + 0) * 512 + i] = hv.x;
    g_hRow[(b0 + 1) * 512 + i] = hv.y;
    g_hRow[(b0 + 2) * 512 + i] = hv.z;
    g_hRow[(b0 + 3) * 512 + i] = hv.w;
}

// ------ attention partials: register-direct, warp = 4 timesteps (R12) ------
__global__ void attn_part_kernel(const float* __restrict__ lf)
{
    __shared__ float e_s[TCH];
    __shared__ __align__(16) float csh[8 * 132];
    int b = blockIdx.x & 31, hh = blockIdx.x >> 5;
    int part = blockIdx.y;
    int t0 = part * TCH;
    int tid = threadIdx.x, lane = tid & 31, w = tid >> 5;

    float4 ds4 = ((const float4*)(g_hRow + b * 512 + hh * 128))[lane];

    const float4* src = (const float4*)(lf + ((size_t)b * TT + t0) * 512 + hh * 128);
    float4 v0 = src[(size_t)(w * 4 + 0) * 128 + lane];
    float4 v1 = src[(size_t)(w * 4 + 1) * 128 + lane];
    float4 v2 = src[(size_t)(w * 4 + 2) * 128 + lane];
    float4 v3 = src[(size_t)(w * 4 + 3) * 128 + lane];

    float a0 = ds4.x * v0.x + ds4.y * v0.y + ds4.z * v0.z + ds4.w * v0.w;
    float a1 = ds4.x * v1.x + ds4.y * v1.y + ds4.z * v1.z + ds4.w * v1.w;
    float a2 = ds4.x * v2.x + ds4.y * v2.y + ds4.z * v2.z + ds4.w * v2.w;
    float a3 = ds4.x * v3.x + ds4.y * v3.y + ds4.z * v3.z + ds4.w * v3.w;
    #pragma unroll
    for (int off = 16; off; off >>= 1) {
        a0 += __shfl_xor_sync(~0u, a0, off);
        a1 += __shfl_xor_sync(~0u, a1, off);
        a2 += __shfl_xor_sync(~0u, a2, off);
        a3 += __shfl_xor_sync(~0u, a3, off);
    }
    if (lane == 0) {
        e_s[w * 4 + 0] = a0; e_s[w * 4 + 1] = a1;
        e_s[w * 4 + 2] = a2; e_s[w * 4 + 3] = a3;
    }
    __syncthreads();

    int bh = b * 4 + hh;
    if (tid < 32) {
        float e = e_s[tid];
        if (hh == 3) g_eBuf[b * TT + t0 + tid] = e;
        float m = e;
        #pragma unroll
        for (int off = 16; off; off >>= 1) m = fmaxf(m, __shfl_xor_sync(~0u, m, off));
        float p = __expf(e - m);
        e_s[tid] = p;
        float s = p;
        #pragma unroll
        for (int off = 16; off; off >>= 1) s += __shfl_xor_sync(~0u, s, off);
        if (tid == 0) { g_mP[part * 128 + bh] = m; g_sP[part * 128 + bh] = s; }
    }
    __syncthreads();

    float p0 = e_s[w * 4 + 0], p1 = e_s[w * 4 + 1];
    float p2 = e_s[w * 4 + 2], p3 = e_s[w * 4 + 3];
    float4 acc;
    acc.x = p0 * v0.x + p1 * v1.x + p2 * v2.x + p3 * v3.x;
    acc.y = p0 * v0.y + p1 * v1.y + p2 * v2.y + p3 * v3.y;
    acc.z = p0 * v0.z + p1 * v1.z + p2 * v2.z + p3 * v3.z;
    acc.w = p0 * v0.w + p1 * v1.w + p2 * v2.w + p3 * v3.w;
    ((float4*)&csh[w * 132])[lane] = acc;
    __syncthreads();

    if (tid < 128) {
        float ss = 0.f;
        #pragma unroll
        for (int q = 0; q < 8; q++) ss += csh[q * 132 + tid];
        g_ctxP[part][bh * 128 + tid] = ss;
    }
}

// ---------------- attention combine (NP=32) ----------------
__global__ void attn_combine_kernel(float* __restrict__ attn_out)
{
    int b = blockIdx.x & 31, hh = blockIdx.x >> 5;
    int bh = b * 4 + hh;
    int tid = threadIdx.x;   // 128
    __shared__ float w_s[NP];
    __shared__ float Ms, Ss;

    if (tid < 32) {
        float m = g_mP[tid * 128 + bh];
        float sp = g_sP[tid * 128 + bh];
        float M = m;
        #pragma unroll
        for (int off = 16; off; off >>= 1) M = fmaxf(M, __shfl_xor_sync(~0u, M, off));
        float w = __expf(m - M);
        w_s[tid] = w;
        float s = sp * w;
        #pragma unroll
        for (int off = 16; off; off >>= 1) s += __shfl_xor_sync(~0u, s, off);
        if (tid == 0) { Ms = M; Ss = s; }
    }
    __syncthreads();
    float inv = 1.f / Ss;
    float M = Ms;

    float ctx = 0.f;
    #pragma unroll
    for (int p = 0; p < NP; p++) ctx = fmaf(g_ctxP[p][bh * 128 + tid], w_s[p], ctx);
    ctx *= inv;
    int d = hh * 128 + tid;
    g_actT[(512 + d) * BB + b] = ctx;
    g_hcT[(512 + d) * BB + b] = ctx;

    if (hh == 3) {
        #pragma unroll
        for (int i = 0; i < 8; i++) {
            int t = tid + i * 128;
            __stcs(&attn_out[(size_t)b * TT + t], __expf(g_eBuf[b * TT + t] - M) * inv);
        }
    }
}

// ------- predict_hid split GEMM: K-split x8, smem-staged weights -------
__global__ void hid_split_kernel(const float* __restrict__ Wp)
{
    __shared__ float ws[16 * 129];
    const int j0 = blockIdx.x * 16;       // 32 j-tiles
    const int base = blockIdx.y * 128;    // 8 K-parts
    for (int idx = threadIdx.x; idx < 16 * 128; idx += 128) {
        int r = idx >> 7, kk = idx & 127;
        ws[r * 129 + kk] = Wp[(size_t)(j0 + r) * 1024 + base + kk];
    }
    __syncthreads();

    int bg = threadIdx.x & 7, jj = threadIdx.x >> 3;
    const float* wr = ws + jj * 129;
    const float4* xv = (const float4*)g_hcT;
    float ax = 0.f, ay = 0.f, az = 0.f, aw = 0.f;
    #pragma unroll 8
    for (int kk = 0; kk < 128; kk++) {
        float w = wr[kk];
        float4 x = xv[(base + kk) * 8 + bg];
        ax = fmaf(w, x.x, ax); ay = fmaf(w, x.y, ay);
        az = fmaf(w, x.z, az); aw = fmaf(w, x.w, aw);
    }
    ((float4*)g_hidP[blockIdx.y])[(j0 + jj) * 8 + bg] = make_float4(ax, ay, az, aw);
}

// ------- hid reduce: sum 8 partials + bias + relu -------
__global__ void hid_reduce_kernel(const float* __restrict__ bp)
{
    int idx = blockIdx.x * blockDim.x + threadIdx.x;   // 4096 float4 items
    if (idx >= 512 * 8) return;
    int j = idx >> 3;
    float4 v = make_float4(0.f, 0.f, 0.f, 0.f);
    #pragma unroll
    for (int p = 0; p < HKS; p++) {
        float4 x = ((const float4*)g_hidP[p])[idx];
        v.x += x.x; v.y += x.y; v.z += x.z; v.w += x.w;
    }
    float bias = bp[j];
    v.x = fmaxf(v.x + bias, 0.f); v.y = fmaxf(v.y + bias, 0.f);
    v.z = fmaxf(v.z + bias, 0.f); v.w = fmaxf(v.w + bias, 0.f);
    ((float4*)g_hidT)[idx] = v;
}

// ------- logits GEMM, K-split x4, 32 j/block, 2-j register blocking -------
__global__ void logits_gemm_kernel(const float* __restrict__ Wc)
{
    __shared__ float ws[32 * 129];
    const int j0 = blockIdx.x * 32;
    const int base = blockIdx.y * 128;
    for (int idx = threadIdx.x; idx < 32 * 128; idx += 128) {
        int r = idx >> 7, kk = idx & 127;
        int j = j0 + r;
        ws[r * 129 + kk] = (j < VV) ? Wc[(size_t)j * 512 + base + kk] : 0.f;
    }
    __syncthreads();

    int bg = threadIdx.x & 7, jp = threadIdx.x >> 3;   // jp 0..15
    const float* wr0 = ws + (jp * 2) * 129;
    const float* wr1 = wr0 + 129;
    const float4* xv = (const float4*)g_hidT;
    float a0x = 0.f, a0y = 0.f, a0z = 0.f, a0w = 0.f;
    float a1x = 0.f, a1y = 0.f, a1z = 0.f, a1w = 0.f;
    #pragma unroll 8
    for (int kk = 0; kk < 128; kk++) {
        float w0 = wr0[kk], w1 = wr1[kk];
        float4 x = xv[(base + kk) * 8 + bg];
        a0x = fmaf(w0, x.x, a0x); a0y = fmaf(w0, x.y, a0y);
        a0z = fmaf(w0, x.z, a0z); a0w = fmaf(w0, x.w, a0w);
        a1x = fmaf(w1, x.x, a1x); a1y = fmaf(w1, x.y, a1y);
        a1z = fmaf(w1, x.z, a1z); a1w = fmaf(w1, x.w, a1w);
    }
    int j = j0 + jp * 2;
    float* dst = g_logitsP[blockIdx.y];
    int b0 = bg * 4;
    if (j < VV) {
        dst[(size_t)(b0 + 0) * JPAD + j] = a0x;
        dst[(size_t)(b0 + 1) * JPAD + j] = a0y;
        dst[(size_t)(b0 + 2) * JPAD + j] = a0z;
        dst[(size_t)(b0 + 3) * JPAD + j] = a0w;
    }
    if (j + 1 < VV) {
        dst[(size_t)(b0 + 0) * JPAD + j + 1] = a1x;
        dst[(size_t)(b0 + 1) * JPAD + j + 1] = a1y;
        dst[(size_t)(b0 + 2) * JPAD + j + 1] = a1z;
        dst[(size_t)(b0 + 3) * JPAD + j + 1] = a1w;
    }
}

// ------- log_softmax + argmax + pred row + next embedding -----
__global__ void lsm_kernel(const float* __restrict__ bc, const float* __restrict__ emb,
                           float* __restrict__ out_pred)
{
    int b = blockIdx.x;
    int tid = threadIdx.x;   // 1024
    __shared__ float v_s[VV];
    __shared__ float sv[1024];
    __shared__ int   si[1024];
    __shared__ int   tok_s;

    const float4* p0 = (const float4*)(g_logitsP[0] + (size_t)b * JPAD);
    const float4* p1 = (const float4*)(g_logitsP[1] + (size_t)b * JPAD);
    const float4* p2 = (const float4*)(g_logitsP[2] + (size_t)b * JPAD);
    const float4* p3 = (const float4*)(g_logitsP[3] + (size_t)b * JPAD);
    const float4* bcv = (const float4*)bc;
    for (int j4 = tid; j4 < VV / 4; j4 += 1024) {
        float4 a = p0[j4], c = p1[j4], d = p2[j4], e = p3[j4], f = bcv[j4];
        float4 r;
        r.x = a.x + c.x + d.x + e.x + f.x;
        r.y = a.y + c.y + d.y + e.y + f.y;
        r.z = a.z + c.z + d.z + e.z + f.z;
        r.w = a.w + c.w + d.w + e.w + f.w;
        ((float4*)v_s)[j4] = r;
    }
    __syncthreads();

    float m = -1e30f; int mi = VV;
    for (int j = tid; j < VV; j += 1024) {
        float v = v_s[j];
        if (v > m) { m = v; mi = j; }
    }
    sv[tid] = m; si[tid] = mi; __syncthreads();
    for (int st = 512; st; st >>= 1) {
        if (tid < st) {
            float v2 = sv[tid + st]; int i2 = si[tid + st];
            if (v2 > sv[tid] || (v2 == sv[tid] && i2 < si[tid])) { sv[tid] = v2; si[tid] = i2; }
        }
        __syncthreads();
    }
    float mm = sv[0];
    if (tid == 0) tok_s = si[0];
    __syncthreads();

    float s = 0.f;
    for (int j = tid; j < VV; j += 1024) s += __expf(v_s[j] - mm);
    sv[tid] = s; __syncthreads();
    for (int st = 512; st; st >>= 1) { if (tid < st) sv[tid] += sv[tid + st]; __syncthreads(); }
    float lse = mm + logf(sv[0]);

    float4* row = (float4*)(out_pred + (size_t)b * VV);
    for (int j4 = tid; j4 < VV / 4; j4 += 1024) {
        float4 v = ((float4*)v_s)[j4];
        v.x -= lse; v.y -= lse; v.z -= lse; v.w -= lse;
        __stcs(&row[j4], v);
    }

    int tok = tok_s;
    if (tid < 512) g_actT[tid * BB + b] = emb[(size_t)tok * 512 + tid];
}

// ---------------- launcher ----------------
extern "C" void kernel_launch(void* const* d_in, const int* in_sizes, int n_in,
                              void* d_out, int out_size)
{
    const float* lf   = (const float*)d_in[0];
    const float* emb  = (const float*)d_in[1];
    const float* W_ih = (const float*)d_in[2];
    const float* W_hh = (const float*)d_in[3];
    const float* b_ih = (const float*)d_in[4];
    const float* b_hh = (const float*)d_in[5];
    const float* Wp   = (const float*)d_in[6];
    const float* bp   = (const float*)d_in[7];
    const float* Wc   = (const float*)d_in[8];
    const float* bc   = (const float*)d_in[9];

    float* out      = (float*)d_out;
    float* out_pred = out;
    float* out_attn = out + (size_t)STEPS * BB * VV;

    init_kernel<<<192, 256>>>(emb, lf);

    for (int s = 0; s < STEPS; s++) {
        gates_gemm_kernel<<<dim3(64, GKS), 128>>>(W_ih, W_hh);
        lstm_pointwise_kernel<<<32, 128>>>(b_ih, b_hh);
        attn_part_kernel<<<dim3(128, NP), 256>>>(lf);
        attn_combine_kernel<<<128, 128>>>(out_attn + (size_t)s * BB * TT);
        hid_split_kernel<<<dim3(32, HKS), 128>>>(Wp);
        hid_reduce_kernel<<<16, 256>>>(bp);
        logits_gemm_kernel<<<dim3(157, LKS), 128>>>(Wc);
        lsm_kernel<<<32, 1024>>>(bc, emb, out_pred + (size_t)s * BB * VV);
    }
}